// round 10
// baseline (speedup 1.0000x reference)
#include <cuda_runtime.h>
#include <cuda_fp16.h>
#include <math.h>

#define NN 50000
#define NE 800000
#define DIM 128
#define NH 8
#define HD 16
#define NET 5

// ---- scratch (device globals; no allocation allowed) ----
__device__ float  gQ[NN * DIM];
__device__ __half gKtH[NET * NN * DIM];  // K transformed, fp16 (64MB)
__device__ __half gVH[NN * DIM];         // V, fp16 (12.8MB)
__device__ float  gAgg[NN * DIM];
__device__ float  gHid[NN * DIM];
__device__ float  gF1[NN * 4 * DIM];
__device__ int    gEid[NE];              // packed: (etype<<20) | src
__device__ int    gCnt[NN];
__device__ int    gCur[NN];
__device__ int    gRow[NN + 1];
__device__ int    gBlkSum[64];
__device__ int    gBlkOff[64];

// ---------------------------------------------------------------------------
__global__ void init_kernel(int N) {
    int i = blockIdx.x * blockDim.x + threadIdx.x;
    if (i < N) { gCnt[i] = 0; gCur[i] = 0; }
}

// ---------------------------------------------------------------------------
// QKV + Kt v2: weights cached in smem ONCE per block; 512 thr = 4 node-groups.
// Per-group named barriers; each group processes one node per iteration.
// ---------------------------------------------------------------------------
__global__ void qkv_kt_kernel(const float* __restrict__ x,
                              const int* __restrict__ node_type,
                              const float* __restrict__ WQ,
                              const float* __restrict__ WK,
                              const float* __restrict__ WV,
                              const float* __restrict__ We, int N) {
    extern __shared__ float sw[];
    float* sWQ = sw;               // 6144 floats
    float* sWK = sw + 6144;        // 6144
    float* sWV = sw + 12288;       // 6144
    float* sWe = sw + 18432;       // 10240
    float* sx  = sw + 28672;       // 4 * 128
    float* sk  = sw + 29184;       // 4 * 128

    int tid = threadIdx.x;
    for (int i = tid; i < 6144; i += 512) {
        sWQ[i] = WQ[i]; sWK[i] = WK[i]; sWV[i] = WV[i];
    }
    for (int i = tid; i < 10240; i += 512) sWe[i] = We[i];
    __syncthreads();

    int grp = tid >> 7;            // node group 0..3
    int wt = tid & 127;
    int h = wt >> 4, f = wt & 15;
    int barid = grp + 1;

    for (int n = blockIdx.x * 4 + grp; n < N; n += gridDim.x * 4) {
        sx[grp * 128 + wt] = x[n * 128 + wt];
        asm volatile("bar.sync %0, 128;" :: "r"(barid) : "memory");
        int t = node_type[n];
        const float* xr = sx + grp * 128 + h * HD;
        int base = ((t * NH + h) * HD) * HD + f;
        float q = 0.f, k = 0.f, v = 0.f;
#pragma unroll
        for (int d = 0; d < HD; d++) {
            float xv = xr[d];
            q = fmaf(xv, sWQ[base + d * HD], q);
            k = fmaf(xv, sWK[base + d * HD], k);
            v = fmaf(xv, sWV[base + d * HD], v);
        }
        gQ[n * DIM + wt] = q;
        gVH[n * DIM + wt] = __float2half(v);
        sk[grp * 128 + wt] = k;
        asm volatile("bar.sync %0, 128;" :: "r"(barid) : "memory");
        const float* kr = sk + grp * 128 + h * HD;
#pragma unroll
        for (int et = 0; et < NET; et++) {
            const float* w = sWe + ((et * NH + h) * HD) * HD + f;
            float acc = 0.f;
#pragma unroll
            for (int d = 0; d < HD; d++) acc = fmaf(kr[d], w[d * HD], acc);
            gKtH[(et * NN + n) * DIM + wt] = __float2half(acc);
        }
        asm volatile("bar.sync %0, 128;" :: "r"(barid) : "memory");
    }
}

// ---------------------------------------------------------------------------
// CSR build
// ---------------------------------------------------------------------------
__global__ void hist_kernel(const int* __restrict__ ei, int E) {
    int e = blockIdx.x * blockDim.x + threadIdx.x;
    if (e < E) atomicAdd(&gCnt[ei[E + e]], 1);
}

__global__ void scan_local_kernel(int N) {
    __shared__ int sh[1024];
    int t = threadIdx.x;
    int i = blockIdx.x * 1024 + t;
    int v = (i < N) ? gCnt[i] : 0;
    sh[t] = v;
    __syncthreads();
#pragma unroll
    for (int off = 1; off < 1024; off <<= 1) {
        int add = (t >= off) ? sh[t - off] : 0;
        __syncthreads();
        sh[t] += add;
        __syncthreads();
    }
    if (i < N) gRow[i] = sh[t] - v;
    if (t == 1023) gBlkSum[blockIdx.x] = sh[1023];
}

__global__ void scan_block_kernel(int nblk) {
    __shared__ int sh[64];
    int t = threadIdx.x;
    int v = (t < nblk) ? gBlkSum[t] : 0;
    sh[t] = v;
    __syncthreads();
#pragma unroll
    for (int off = 1; off < 64; off <<= 1) {
        int add = (t >= off) ? sh[t - off] : 0;
        __syncthreads();
        sh[t] += add;
        __syncthreads();
    }
    gBlkOff[t] = sh[t] - v;
}

__global__ void scan_add_kernel(int N, int E) {
    int i = blockIdx.x * blockDim.x + threadIdx.x;
    if (i < N) gRow[i] += gBlkOff[i >> 10];
    if (i == 0) gRow[N] = E;
}

// pack (etype<<20 | src): attention does ONE indexed load per edge
__global__ void fill_kernel(const int* __restrict__ ei,
                            const int* __restrict__ etype, int E) {
    int e = blockIdx.x * blockDim.x + threadIdx.x;
    if (e < E) {
        int dst = ei[E + e];
        int p = atomicAdd(&gCur[dst], 1);
        gEid[gRow[dst] + p] = (etype[e] << 20) | ei[e];
    }
}

// ---------------------------------------------------------------------------
// fused attention v4: warp-per-edge (4 in flight), tile=32, V co-gathered in
// phase 1 and held in REGISTERS (<=8 unrolled slots) -> phase 3 is pure FMA.
// One gather drain per tile instead of two.
// ---------------------------------------------------------------------------
__global__ void attn_kernel(const float* __restrict__ mu, int E) {
    int n = blockIdx.x;
    int tid = threadIdx.x;
    int lane = tid & 31;
    int grp = tid >> 5;             // warp index = edge slot
    int h = lane >> 2;              // head
    int f4 = lane & 3;              // dim quad within head
    int d0 = h * HD + 4 * f4;

    __shared__ int s_pk[32];
    __shared__ float s_sc[32][9];
    __shared__ float m_sh[8], den_sh[8], scale_sh[8];
    __shared__ float s_merge[4][DIM];

    float4 q = *(const float4*)&gQ[n * DIM + d0];
    float muh[NET];
#pragma unroll
    for (int et = 0; et < NET; et++) muh[et] = mu[h * NET + et] * 0.25f;

    if (tid < 8) { m_sh[tid] = -3.402823466e38f; den_sh[tid] = 0.f; }
    float4 acc = make_float4(0.f, 0.f, 0.f, 0.f);
    __syncthreads();

    int row0 = gRow[n], row1 = gRow[n + 1];
    for (int cs = row0; cs < row1; cs += 32) {
        int c = min(32, row1 - cs);
        if (tid < c) s_pk[tid] = gEid[cs + tid];
        __syncthreads();

        // ---- phase 1: scores + V into registers (co-issued gathers) ----
        float4 vreg[8];
#pragma unroll
        for (int it = 0; it < 8; it++) {
            int j = grp + it * 4;
            if (j >= c) break;
            int pk = s_pk[j];
            int src = pk & 0xFFFFF, et = pk >> 20;
            uint2 kraw = *(const uint2*)&gKtH[(et * NN + src) * DIM + d0];
            uint2 vraw = *(const uint2*)&gVH[src * DIM + d0];
            float2 ka = __half22float2(*(__half2*)&kraw.x);
            float2 kb = __half22float2(*(__half2*)&kraw.y);
            float2 va = __half22float2(*(__half2*)&vraw.x);
            float2 vb = __half22float2(*(__half2*)&vraw.y);
            vreg[it] = make_float4(va.x, va.y, vb.x, vb.y);
            float s = q.x * ka.x + q.y * ka.y + q.z * kb.x + q.w * kb.y;
            s += __shfl_xor_sync(0xffffffffu, s, 1);
            s += __shfl_xor_sync(0xffffffffu, s, 2);
            if (f4 == 0) s_sc[j][h] = s * muh[et];
        }
        __syncthreads();

        // ---- phase 2: warp 0 updates per-head stats over the tile ----
        if (grp == 0) {
            float tmax = -3.402823466e38f;
            for (int j = f4; j < c; j += 4) tmax = fmaxf(tmax, s_sc[j][h]);
            tmax = fmaxf(tmax, __shfl_xor_sync(0xffffffffu, tmax, 1));
            tmax = fmaxf(tmax, __shfl_xor_sync(0xffffffffu, tmax, 2));
            float mold = m_sh[h];
            float newm = fmaxf(mold, tmax);
            float dt = 0.f;
            for (int j = f4; j < c; j += 4) {
                float w = __expf(s_sc[j][h] - newm);
                s_sc[j][h] = w;
                dt += w;
            }
            dt += __shfl_xor_sync(0xffffffffu, dt, 1);
            dt += __shfl_xor_sync(0xffffffffu, dt, 2);
            if (f4 == 0) {
                float sc = __expf(mold - newm);
                den_sh[h] = den_sh[h] * sc + dt;
                m_sh[h] = newm;
                scale_sh[h] = sc;
            }
        }
        __syncthreads();

        // ---- phase 3: rescale + weighted V from registers ----
        float sc = scale_sh[h];
        acc.x *= sc; acc.y *= sc; acc.z *= sc; acc.w *= sc;
#pragma unroll
        for (int it = 0; it < 8; it++) {
            int j = grp + it * 4;
            if (j >= c) break;
            float w = s_sc[j][h];
            acc.x = fmaf(w, vreg[it].x, acc.x);
            acc.y = fmaf(w, vreg[it].y, acc.y);
            acc.z = fmaf(w, vreg[it].z, acc.z);
            acc.w = fmaf(w, vreg[it].w, acc.w);
        }
        __syncthreads();
    }

    // ---- merge the 4 per-warp partials ----
    *(float4*)&s_merge[grp][d0] = acc;
    __syncthreads();
    float tot = s_merge[0][tid] + s_merge[1][tid] + s_merge[2][tid] + s_merge[3][tid];
    gAgg[n * DIM + tid] = tot / (den_sh[tid >> 4] + 1e-10f);
}

// ---------------------------------------------------------------------------
// tf32 tensor-core machinery
// ---------------------------------------------------------------------------
__device__ __forceinline__ unsigned f2tf(float f) {
    unsigned r;
    asm("cvt.rna.tf32.f32 %0, %1;" : "=r"(r) : "f"(f));
    return r;
}
__device__ __forceinline__ void mma_tf32(float* c, const unsigned* a, const unsigned* b) {
    asm volatile(
        "mma.sync.aligned.m16n8k8.row.col.f32.tf32.tf32.f32 "
        "{%0,%1,%2,%3},{%4,%5,%6,%7},{%8,%9},{%0,%1,%2,%3};"
        : "+f"(c[0]), "+f"(c[1]), "+f"(c[2]), "+f"(c[3])
        : "r"(a[0]), "r"(a[1]), "r"(a[2]), "r"(a[3]), "r"(b[0]), "r"(b[1]));
}

// ---------------------------------------------------------------------------
// oproj tf32: gHid = LN1(x + gAgg @ Wo + bo); 512 thr, 128-row tiles, K=128
// ---------------------------------------------------------------------------
__global__ void oproj_tc_ln1(const float* __restrict__ x,
                             const float* __restrict__ Wo,
                             const float* __restrict__ bo,
                             const float* __restrict__ g1,
                             const float* __restrict__ bb1, int M) {
    __shared__ unsigned As[128][36];
    __shared__ unsigned Bs[32][132];
    __shared__ float rs[4][128];
    __shared__ float rq[4][128];
    int tid = threadIdx.x, lane = tid & 31, wid = tid >> 5;
    int wy = (wid & 3) * 32, wxg = wid >> 2;
    int wx = wxg * 32;
    int m0 = blockIdx.y * 128;
    int r = lane >> 2, t = lane & 3;
    float c[2][4][4];
#pragma unroll
    for (int i = 0; i < 2; i++)
#pragma unroll
        for (int j = 0; j < 4; j++)
#pragma unroll
            for (int q = 0; q < 4; q++) c[i][j][q] = 0.f;

    for (int k0 = 0; k0 < 128; k0 += 32) {
#pragma unroll
        for (int l = tid; l < 1024; l += 512) {
            int m = l >> 3, kq = (l & 7) << 2;
            int gm = m0 + m; if (gm >= M) gm = M - 1;
            float4 a = *(const float4*)(&gAgg[gm * 128 + k0 + kq]);
            As[m][kq] = f2tf(a.x); As[m][kq + 1] = f2tf(a.y);
            As[m][kq + 2] = f2tf(a.z); As[m][kq + 3] = f2tf(a.w);
        }
#pragma unroll
        for (int l = tid; l < 1024; l += 512) {
            int k = l >> 5, nq = (l & 31) << 2;
            float4 b = *(const float4*)(&Wo[(k0 + k) * 128 + nq]);
            Bs[k][nq] = f2tf(b.x); Bs[k][nq + 1] = f2tf(b.y);
            Bs[k][nq + 2] = f2tf(b.z); Bs[k][nq + 3] = f2tf(b.w);
        }
        __syncthreads();
#pragma unroll
        for (int kk = 0; kk < 32; kk += 8) {
            unsigned af[2][4], bf[4][2];
#pragma unroll
            for (int i = 0; i < 2; i++) {
                af[i][0] = As[wy + i * 16 + r][kk + t];
                af[i][1] = As[wy + i * 16 + r + 8][kk + t];
                af[i][2] = As[wy + i * 16 + r][kk + t + 4];
                af[i][3] = As[wy + i * 16 + r + 8][kk + t + 4];
            }
#pragma unroll
            for (int j = 0; j < 4; j++) {
                bf[j][0] = Bs[kk + t][wx + j * 8 + r];
                bf[j][1] = Bs[kk + t + 4][wx + j * 8 + r];
            }
#pragma unroll
            for (int i = 0; i < 2; i++)
#pragma unroll
                for (int j = 0; j < 4; j++) mma_tf32(c[i][j], af[i], bf[j]);
        }
        __syncthreads();
    }

    float sum[2][2] = {{0.f, 0.f}, {0.f, 0.f}};
    float sq2[2][2] = {{0.f, 0.f}, {0.f, 0.f}};
#pragma unroll
    for (int i = 0; i < 2; i++) {
        int row = m0 + wy + i * 16 + r;
        int rowc  = (row < M) ? row : (M - 1);
        int row2c = (row + 8 < M) ? (row + 8) : (M - 1);
#pragma unroll
        for (int j = 0; j < 4; j++) {
            int col = wx + j * 8 + 2 * t;
            float bc0 = bo[col], bc1 = bo[col + 1];
            float2 h0 = *(const float2*)&x[rowc * 128 + col];
            float2 h1 = *(const float2*)&x[row2c * 128 + col];
            c[i][j][0] += bc0 + h0.x;
            c[i][j][1] += bc1 + h0.y;
            c[i][j][2] += bc0 + h1.x;
            c[i][j][3] += bc1 + h1.y;
            sum[i][0] += c[i][j][0] + c[i][j][1];
            sum[i][1] += c[i][j][2] + c[i][j][3];
            sq2[i][0] = fmaf(c[i][j][0], c[i][j][0], fmaf(c[i][j][1], c[i][j][1], sq2[i][0]));
            sq2[i][1] = fmaf(c[i][j][2], c[i][j][2], fmaf(c[i][j][3], c[i][j][3], sq2[i][1]));
        }
    }
#pragma unroll
    for (int i = 0; i < 2; i++) {
#pragma unroll
        for (int hl = 0; hl < 2; hl++) {
            sum[i][hl] += __shfl_xor_sync(0xffffffffu, sum[i][hl], 1);
            sum[i][hl] += __shfl_xor_sync(0xffffffffu, sum[i][hl], 2);
            sq2[i][hl] += __shfl_xor_sync(0xffffffffu, sq2[i][hl], 1);
            sq2[i][hl] += __shfl_xor_sync(0xffffffffu, sq2[i][hl], 2);
        }
    }
    if (t == 0) {
#pragma unroll
        for (int i = 0; i < 2; i++) {
            rs[wxg][wy + i * 16 + r]     = sum[i][0];
            rs[wxg][wy + i * 16 + r + 8] = sum[i][1];
            rq[wxg][wy + i * 16 + r]     = sq2[i][0];
            rq[wxg][wy + i * 16 + r + 8] = sq2[i][1];
        }
    }
    __syncthreads();
#pragma unroll
    for (int i = 0; i < 2; i++) {
#pragma unroll
        for (int hl = 0; hl < 2; hl++) {
            int rl = wy + i * 16 + r + hl * 8;
            int row = m0 + rl;
            float s  = rs[0][rl] + rs[1][rl] + rs[2][rl] + rs[3][rl];
            float s2 = rq[0][rl] + rq[1][rl] + rq[2][rl] + rq[3][rl];
            float mean = s * (1.f / DIM);
            float var = s2 * (1.f / DIM) - mean * mean;
            float rstd = rsqrtf(var + 1e-5f);
            if (row < M) {
#pragma unroll
                for (int j = 0; j < 4; j++) {
                    int col = wx + j * 8 + 2 * t;
                    float y0 = c[i][j][hl * 2 + 0];
                    float y1 = c[i][j][hl * 2 + 1];
                    float o0 = (y0 - mean) * rstd * g1[col] + bb1[col];
                    float o1 = (y1 - mean) * rstd * g1[col + 1] + bb1[col + 1];
                    *(float2*)&gHid[row * 128 + col] = make_float2(o0, o1);
                }
            }
        }
    }
}

// ---------------------------------------------------------------------------
// FFN1: gF1[M,512] = gelu(gHid[M,128] @ W1 + b1); 512 thr (R6-validated)
// ---------------------------------------------------------------------------
__global__ void ffn1_tc(const float* __restrict__ W1,
                        const float* __restrict__ b1v, int M) {
    __shared__ unsigned As[128][36];
    __shared__ unsigned Bs[32][132];
    int tid = threadIdx.x, lane = tid & 31, wid = tid >> 5;
    int wy = (wid & 3) * 32, wx = (wid >> 2) * 32;
    int m0 = blockIdx.y * 128, n0 = blockIdx.x * 128;
    int r = lane >> 2, t = lane & 3;
    float c[2][4][4];
#pragma unroll
    for (int i = 0; i < 2; i++)
#pragma unroll
        for (int j = 0; j < 4; j++)
#pragma unroll
            for (int q = 0; q < 4; q++) c[i][j][q] = 0.f;

    for (int k0 = 0; k0 < 128; k0 += 32) {
#pragma unroll
        for (int l = tid; l < 1024; l += 512) {
            int m = l >> 3, kq = (l & 7) << 2;
            int gm = m0 + m; if (gm >= M) gm = M - 1;
            float4 a = *(const float4*)(&gHid[gm * 128 + k0 + kq]);
            As[m][kq] = f2tf(a.x); As[m][kq + 1] = f2tf(a.y);
            As[m][kq + 2] = f2tf(a.z); As[m][kq + 3] = f2tf(a.w);
        }
#pragma unroll
        for (int l = tid; l < 1024; l += 512) {
            int k = l >> 5, nq = (l & 31) << 2;
            float4 b = *(const float4*)(&W1[(k0 + k) * 512 + n0 + nq]);
            Bs[k][nq] = f2tf(b.x); Bs[k][nq + 1] = f2tf(b.y);
            Bs[k][nq + 2] = f2tf(b.z); Bs[k][nq + 3] = f2tf(b.w);
        }
        __syncthreads();
#pragma unroll
        for (int kk = 0; kk < 32; kk += 8) {
            unsigned af[2][4], bf[4][2];
#pragma unroll
            for (int i = 0; i < 2; i++) {
                af[i][0] = As[wy + i * 16 + r][kk + t];
                af[i][1] = As[wy + i * 16 + r + 8][kk + t];
                af[i][2] = As[wy + i * 16 + r][kk + t + 4];
                af[i][3] = As[wy + i * 16 + r + 8][kk + t + 4];
            }
#pragma unroll
            for (int j = 0; j < 4; j++) {
                bf[j][0] = Bs[kk + t][wx + j * 8 + r];
                bf[j][1] = Bs[kk + t + 4][wx + j * 8 + r];
            }
#pragma unroll
            for (int i = 0; i < 2; i++)
#pragma unroll
                for (int j = 0; j < 4; j++) mma_tf32(c[i][j], af[i], bf[j]);
        }
        __syncthreads();
    }
#pragma unroll
    for (int i = 0; i < 2; i++) {
        int row = m0 + wy + i * 16 + r;
        int row2 = row + 8;
#pragma unroll
        for (int j = 0; j < 4; j++) {
            int col = n0 + wx + j * 8 + 2 * t;
            float bc0 = b1v[col], bc1 = b1v[col + 1];
            if (row < M) {
                float v0 = c[i][j][0] + bc0;
                float v1 = c[i][j][1] + bc1;
                v0 = 0.5f * v0 * (1.f + erff(v0 * 0.7071067811865476f));
                v1 = 0.5f * v1 * (1.f + erff(v1 * 0.7071067811865476f));
                *(float2*)&gF1[row * 512 + col] = make_float2(v0, v1);
            }
            if (row2 < M) {
                float v0 = c[i][j][2] + bc0;
                float v1 = c[i][j][3] + bc1;
                v0 = 0.5f * v0 * (1.f + erff(v0 * 0.7071067811865476f));
                v1 = 0.5f * v1 * (1.f + erff(v1 * 0.7071067811865476f));
                *(float2*)&gF1[row2 * 512 + col] = make_float2(v0, v1);
            }
        }
    }
}

// ---------------------------------------------------------------------------
// FFN2: out = LN2(gHid + gF1[M,512] @ W2 + b2); 512 thr (R6-validated)
// ---------------------------------------------------------------------------
__global__ void ffn2_tc_ln2(const float* __restrict__ W2,
                            const float* __restrict__ b2v,
                            const float* __restrict__ g2,
                            const float* __restrict__ bb2,
                            float* __restrict__ out, int M) {
    __shared__ unsigned As[128][36];
    __shared__ unsigned Bs[32][132];
    __shared__ float rs[4][128];
    __shared__ float rq[4][128];
    int tid = threadIdx.x, lane = tid & 31, wid = tid >> 5;
    int wy = (wid & 3) * 32, wxg = wid >> 2;
    int wx = wxg * 32;
    int m0 = blockIdx.y * 128;
    int r = lane >> 2, t = lane & 3;
    float c[2][4][4];
#pragma unroll
    for (int i = 0; i < 2; i++)
#pragma unroll
        for (int j = 0; j < 4; j++)
#pragma unroll
            for (int q = 0; q < 4; q++) c[i][j][q] = 0.f;

    for (int k0 = 0; k0 < 512; k0 += 32) {
#pragma unroll
        for (int l = tid; l < 1024; l += 512) {
            int m = l >> 3, kq = (l & 7) << 2;
            int gm = m0 + m; if (gm >= M) gm = M - 1;
            float4 a = *(const float4*)(&gF1[gm * 512 + k0 + kq]);
            As[m][kq] = f2tf(a.x); As[m][kq + 1] = f2tf(a.y);
            As[m][kq + 2] = f2tf(a.z); As[m][kq + 3] = f2tf(a.w);
        }
#pragma unroll
        for (int l = tid; l < 1024; l += 512) {
            int k = l >> 5, nq = (l & 31) << 2;
            float4 b = *(const float4*)(&W2[(k0 + k) * 128 + nq]);
            Bs[k][nq] = f2tf(b.x); Bs[k][nq + 1] = f2tf(b.y);
            Bs[k][nq + 2] = f2tf(b.z); Bs[k][nq + 3] = f2tf(b.w);
        }
        __syncthreads();
#pragma unroll
        for (int kk = 0; kk < 32; kk += 8) {
            unsigned af[2][4], bf[4][2];
#pragma unroll
            for (int i = 0; i < 2; i++) {
                af[i][0] = As[wy + i * 16 + r][kk + t];
                af[i][1] = As[wy + i * 16 + r + 8][kk + t];
                af[i][2] = As[wy + i * 16 + r][kk + t + 4];
                af[i][3] = As[wy + i * 16 + r + 8][kk + t + 4];
            }
#pragma unroll
            for (int j = 0; j < 4; j++) {
                bf[j][0] = Bs[kk + t][wx + j * 8 + r];
                bf[j][1] = Bs[kk + t + 4][wx + j * 8 + r];
            }
#pragma unroll
            for (int i = 0; i < 2; i++)
#pragma unroll
                for (int j = 0; j < 4; j++) mma_tf32(c[i][j], af[i], bf[j]);
        }
        __syncthreads();
    }

    float sum[2][2] = {{0.f, 0.f}, {0.f, 0.f}};
    float sq2[2][2] = {{0.f, 0.f}, {0.f, 0.f}};
#pragma unroll
    for (int i = 0; i < 2; i++) {
        int row = m0 + wy + i * 16 + r;
        int rowc  = (row < M) ? row : (M - 1);
        int row2c = (row + 8 < M) ? (row + 8) : (M - 1);
#pragma unroll
        for (int j = 0; j < 4; j++) {
            int col = wx + j * 8 + 2 * t;
            float bc0 = b2v[col], bc1 = b2v[col + 1];
            float2 h0 = *(const float2*)&gHid[rowc * 128 + col];
            float2 h1 = *(const float2*)&gHid[row2c * 128 + col];
            c[i][j][0] += bc0 + h0.x;
            c[i][j][1] += bc1 + h0.y;
            c[i][j][2] += bc0 + h1.x;
            c[i][j][3] += bc1 + h1.y;
            sum[i][0] += c[i][j][0] + c[i][j][1];
            sum[i][1] += c[i][j][2] + c[i][j][3];
            sq2[i][0] = fmaf(c[i][j][0], c[i][j][0], fmaf(c[i][j][1], c[i][j][1], sq2[i][0]));
            sq2[i][1] = fmaf(c[i][j][2], c[i][j][2], fmaf(c[i][j][3], c[i][j][3], sq2[i][1]));
        }
    }
#pragma unroll
    for (int i = 0; i < 2; i++) {
#pragma unroll
        for (int hl = 0; hl < 2; hl++) {
            sum[i][hl] += __shfl_xor_sync(0xffffffffu, sum[i][hl], 1);
            sum[i][hl] += __shfl_xor_sync(0xffffffffu, sum[i][hl], 2);
            sq2[i][hl] += __shfl_xor_sync(0xffffffffu, sq2[i][hl], 1);
            sq2[i][hl] += __shfl_xor_sync(0xffffffffu, sq2[i][hl], 2);
        }
    }
    if (t == 0) {
#pragma unroll
        for (int i = 0; i < 2; i++) {
            rs[wxg][wy + i * 16 + r]     = sum[i][0];
            rs[wxg][wy + i * 16 + r + 8] = sum[i][1];
            rq[wxg][wy + i * 16 + r]     = sq2[i][0];
            rq[wxg][wy + i * 16 + r + 8] = sq2[i][1];
        }
    }
    __syncthreads();
#pragma unroll
    for (int i = 0; i < 2; i++) {
#pragma unroll
        for (int hl = 0; hl < 2; hl++) {
            int rl = wy + i * 16 + r + hl * 8;
            int row = m0 + rl;
            float s  = rs[0][rl] + rs[1][rl] + rs[2][rl] + rs[3][rl];
            float s2 = rq[0][rl] + rq[1][rl] + rq[2][rl] + rq[3][rl];
            float mean = s * (1.f / DIM);
            float var = s2 * (1.f / DIM) - mean * mean;
            float rstd = rsqrtf(var + 1e-5f);
            if (row < M) {
#pragma unroll
                for (int j = 0; j < 4; j++) {
                    int col = wx + j * 8 + 2 * t;
                    float y0 = c[i][j][hl * 2 + 0];
                    float y1 = c[i][j][hl * 2 + 1];
                    float o0 = (y0 - mean) * rstd * g2[col] + bb2[col];
                    float o1 = (y1 - mean) * rstd * g2[col + 1] + bb2[col + 1];
                    *(float2*)&out[row * 128 + col] = make_float2(o0, o1);
                }
            }
        }
    }
}

// ---------------------------------------------------------------------------
extern "C" void kernel_launch(void* const* d_in, const int* in_sizes, int n_in,
                              void* d_out, int out_size) {
    const float* x     = (const float*)d_in[0];
    const int*   ei    = (const int*)d_in[1];
    const int*   etype = (const int*)d_in[2];
    const int*   ntype = (const int*)d_in[3];
    const float* WQ    = (const float*)d_in[4];
    const float* WK    = (const float*)d_in[5];
    const float* WV    = (const float*)d_in[6];
    const float* We    = (const float*)d_in[7];
    const float* mu    = (const float*)d_in[8];
    const float* Wo    = (const float*)d_in[9];
    const float* bo    = (const float*)d_in[10];
    const float* ln1g  = (const float*)d_in[11];
    const float* ln1b  = (const float*)d_in[12];
    const float* W1    = (const float*)d_in[13];
    const float* b1    = (const float*)d_in[14];
    const float* W2    = (const float*)d_in[15];
    const float* b2    = (const float*)d_in[16];
    const float* ln2g  = (const float*)d_in[17];
    const float* ln2b  = (const float*)d_in[18];

    int N = in_sizes[0] / DIM;   // 50000
    int E = in_sizes[1] / 2;     // 800000
    int nblk = (N + 1023) / 1024;
    int mtiles = (N + 127) / 128;

    // qkv smem: 28672 weight floats + 2*512 staging floats
    int qsmem = (28672 + 1024) * 4;
    cudaFuncSetAttribute(qkv_kt_kernel, cudaFuncAttributeMaxDynamicSharedMemorySize, qsmem);

    init_kernel<<<(N + 255) / 256, 256>>>(N);
    qkv_kt_kernel<<<148, 512, qsmem>>>(x, ntype, WQ, WK, WV, We, N);
    hist_kernel<<<(E + 255) / 256, 256>>>(ei, E);
    scan_local_kernel<<<nblk, 1024>>>(N);
    scan_block_kernel<<<1, 64>>>(nblk);
    scan_add_kernel<<<(N + 255) / 256, 256>>>(N, E);
    fill_kernel<<<(E + 255) / 256, 256>>>(ei, etype, E);
    attn_kernel<<<N, 128>>>(mu, E);
    oproj_tc_ln1<<<dim3(1, mtiles), 512>>>(x, Wo, bo, ln1g, ln1b, N);
    ffn1_tc<<<dim3(4, mtiles), 512>>>(W1, b1, N);
    ffn2_tc_ln2<<<dim3(1, mtiles), 512>>>(W2, b2, ln2g, ln2b, (float*)d_out, N);
}

// round 11
// speedup vs baseline: 1.1482x; 1.1482x over previous
#include <cuda_runtime.h>
#include <cuda_fp16.h>
#include <math.h>

#define NN 50000
#define NE 800000
#define DIM 128
#define NH 8
#define HD 16
#define NET 5

// ---- scratch (device globals; no allocation allowed) ----
__device__ float  gQ[NN * DIM];
__device__ __half gKtH[NET * NN * DIM];  // K transformed, fp16 (64MB)
__device__ __half gVH[NN * DIM];         // V, fp16 (12.8MB)
__device__ float  gAgg[NN * DIM];
__device__ float  gHid[NN * DIM];
__device__ __half gF1[NN * 4 * DIM];     // FFN intermediate, fp16 (51MB)
__device__ int    gEid[NE];              // packed: (etype<<20) | src
__device__ int    gCnt[NN];
__device__ int    gCur[NN];
__device__ int    gRow[NN + 1];
__device__ int    gBlkSum[64];
__device__ int    gBlkOff[64];

// ---------------------------------------------------------------------------
__global__ void init_kernel(int N) {
    int i = blockIdx.x * blockDim.x + threadIdx.x;
    if (i < N) { gCnt[i] = 0; gCur[i] = 0; }
}

// ---------------------------------------------------------------------------
// per-node-type QKV + per-edge-type K transform (R9-validated: small blocks,
// weights L1-resident across sequential blocks on each SM)
// ---------------------------------------------------------------------------
__global__ void qkv_kt_kernel(const float* __restrict__ x,
                              const int* __restrict__ node_type,
                              const float* __restrict__ WQ,
                              const float* __restrict__ WK,
                              const float* __restrict__ WV,
                              const float* __restrict__ We) {
    int n = blockIdx.x;
    int tid = threadIdx.x;
    __shared__ float xs[DIM];
    __shared__ float ks[DIM];
    xs[tid] = x[n * DIM + tid];
    __syncthreads();
    int t = node_type[n];
    int h = tid >> 4, f = tid & 15;
    const float* xr = xs + h * HD;
    int base = ((t * NH + h) * HD) * HD + f;
    float q = 0.f, k = 0.f, v = 0.f;
#pragma unroll
    for (int d = 0; d < HD; d++) {
        float xv = xr[d];
        q = fmaf(xv, WQ[base + d * HD], q);
        k = fmaf(xv, WK[base + d * HD], k);
        v = fmaf(xv, WV[base + d * HD], v);
    }
    gQ[n * DIM + tid] = q;
    gVH[n * DIM + tid] = __float2half(v);
    ks[tid] = k;
    __syncthreads();
    const float* kr = ks + h * HD;
#pragma unroll
    for (int et = 0; et < NET; et++) {
        const float* w = We + ((et * NH + h) * HD) * HD + f;
        float acc = 0.f;
#pragma unroll
        for (int d = 0; d < HD; d++) acc = fmaf(kr[d], w[d * HD], acc);
        gKtH[(et * NN + n) * DIM + tid] = __float2half(acc);
    }
}

// ---------------------------------------------------------------------------
// CSR build
// ---------------------------------------------------------------------------
__global__ void hist_kernel(const int* __restrict__ ei, int E) {
    int e = blockIdx.x * blockDim.x + threadIdx.x;
    if (e < E) atomicAdd(&gCnt[ei[E + e]], 1);
}

__global__ void scan_local_kernel(int N) {
    __shared__ int sh[1024];
    int t = threadIdx.x;
    int i = blockIdx.x * 1024 + t;
    int v = (i < N) ? gCnt[i] : 0;
    sh[t] = v;
    __syncthreads();
#pragma unroll
    for (int off = 1; off < 1024; off <<= 1) {
        int add = (t >= off) ? sh[t - off] : 0;
        __syncthreads();
        sh[t] += add;
        __syncthreads();
    }
    if (i < N) gRow[i] = sh[t] - v;
    if (t == 1023) gBlkSum[blockIdx.x] = sh[1023];
}

__global__ void scan_block_kernel(int nblk) {
    __shared__ int sh[64];
    int t = threadIdx.x;
    int v = (t < nblk) ? gBlkSum[t] : 0;
    sh[t] = v;
    __syncthreads();
#pragma unroll
    for (int off = 1; off < 64; off <<= 1) {
        int add = (t >= off) ? sh[t - off] : 0;
        __syncthreads();
        sh[t] += add;
        __syncthreads();
    }
    gBlkOff[t] = sh[t] - v;
}

__global__ void scan_add_kernel(int N, int E) {
    int i = blockIdx.x * blockDim.x + threadIdx.x;
    if (i < N) gRow[i] += gBlkOff[i >> 10];
    if (i == 0) gRow[N] = E;
}

// pack (etype<<20 | src): attention does ONE indexed load per edge
__global__ void fill_kernel(const int* __restrict__ ei,
                            const int* __restrict__ etype, int E) {
    int e = blockIdx.x * blockDim.x + threadIdx.x;
    if (e < E) {
        int dst = ei[E + e];
        int p = atomicAdd(&gCur[dst], 1);
        gEid[gRow[dst] + p] = (etype[e] << 20) | ei[e];
    }
}

// ---------------------------------------------------------------------------
// fused attention v3 (R9-validated): one WARP per edge (4 edges in flight),
// half4 loads, tile=128, per-head stats in smem, partials merged at end.
// ---------------------------------------------------------------------------
__global__ void attn_kernel(const float* __restrict__ mu, int E) {
    int n = blockIdx.x;
    int tid = threadIdx.x;
    int lane = tid & 31;
    int grp = tid >> 5;             // warp index = edge slot
    int h = lane >> 2;              // head
    int f4 = lane & 3;              // dim quad within head
    int d0 = h * HD + 4 * f4;

    __shared__ int s_pk[128];
    __shared__ float s_sc[128][9];
    __shared__ float m_sh[8], den_sh[8], scale_sh[8];
    __shared__ float s_merge[4][DIM];

    float4 q = *(const float4*)&gQ[n * DIM + d0];
    float muh[NET];
#pragma unroll
    for (int et = 0; et < NET; et++) muh[et] = mu[h * NET + et] * 0.25f;

    if (tid < 8) { m_sh[tid] = -3.402823466e38f; den_sh[tid] = 0.f; }
    float4 acc = make_float4(0.f, 0.f, 0.f, 0.f);
    __syncthreads();

    int row0 = gRow[n], row1 = gRow[n + 1];
    for (int cs = row0; cs < row1; cs += 128) {
        int c = min(128, row1 - cs);
        if (tid < c) s_pk[tid] = gEid[cs + tid];
        __syncthreads();

        // ---- phase 1: scores; warp grp handles edges j = grp, grp+4, ... ----
        for (int j = grp; j < c; j += 4) {
            int pk = s_pk[j];
            int src = pk & 0xFFFFF, et = pk >> 20;
            uint2 kraw = *(const uint2*)&gKtH[(et * NN + src) * DIM + d0];
            float2 ka = __half22float2(*(__half2*)&kraw.x);
            float2 kb = __half22float2(*(__half2*)&kraw.y);
            float s = q.x * ka.x + q.y * ka.y + q.z * kb.x + q.w * kb.y;
            s += __shfl_xor_sync(0xffffffffu, s, 1);
            s += __shfl_xor_sync(0xffffffffu, s, 2);
            if (f4 == 0) s_sc[j][h] = s * muh[et];
        }
        __syncthreads();

        // ---- phase 2: warp 0 updates per-head stats over the tile ----
        if (grp == 0) {
            float tmax = -3.402823466e38f;
            for (int j = f4; j < c; j += 4) tmax = fmaxf(tmax, s_sc[j][h]);
            tmax = fmaxf(tmax, __shfl_xor_sync(0xffffffffu, tmax, 1));
            tmax = fmaxf(tmax, __shfl_xor_sync(0xffffffffu, tmax, 2));
            float mold = m_sh[h];
            float newm = fmaxf(mold, tmax);
            float dt = 0.f;
            for (int j = f4; j < c; j += 4) {
                float w = __expf(s_sc[j][h] - newm);
                s_sc[j][h] = w;
                dt += w;
            }
            dt += __shfl_xor_sync(0xffffffffu, dt, 1);
            dt += __shfl_xor_sync(0xffffffffu, dt, 2);
            if (f4 == 0) {
                float sc = __expf(mold - newm);
                den_sh[h] = den_sh[h] * sc + dt;
                m_sh[h] = newm;
                scale_sh[h] = sc;
            }
        }
        __syncthreads();

        // ---- phase 3: rescale + weighted V accumulation ----
        float sc = scale_sh[h];
        acc.x *= sc; acc.y *= sc; acc.z *= sc; acc.w *= sc;
        for (int j = grp; j < c; j += 4) {
            int src = s_pk[j] & 0xFFFFF;
            float w = s_sc[j][h];
            uint2 vraw = *(const uint2*)&gVH[src * DIM + d0];
            float2 va = __half22float2(*(__half2*)&vraw.x);
            float2 vb = __half22float2(*(__half2*)&vraw.y);
            acc.x = fmaf(w, va.x, acc.x);
            acc.y = fmaf(w, va.y, acc.y);
            acc.z = fmaf(w, vb.x, acc.z);
            acc.w = fmaf(w, vb.y, acc.w);
        }
        __syncthreads();
    }

    // ---- merge the 4 per-warp partials ----
    *(float4*)&s_merge[grp][d0] = acc;
    __syncthreads();
    float tot = s_merge[0][tid] + s_merge[1][tid] + s_merge[2][tid] + s_merge[3][tid];
    gAgg[n * DIM + tid] = tot / (den_sh[tid >> 4] + 1e-10f);
}

// ---------------------------------------------------------------------------
// tf32 tensor-core machinery
// ---------------------------------------------------------------------------
__device__ __forceinline__ unsigned f2tf(float f) {
    unsigned r;
    asm("cvt.rna.tf32.f32 %0, %1;" : "=r"(r) : "f"(f));
    return r;
}
__device__ __forceinline__ void mma_tf32(float* c, const unsigned* a, const unsigned* b) {
    asm volatile(
        "mma.sync.aligned.m16n8k8.row.col.f32.tf32.tf32.f32 "
        "{%0,%1,%2,%3},{%4,%5,%6,%7},{%8,%9},{%0,%1,%2,%3};"
        : "+f"(c[0]), "+f"(c[1]), "+f"(c[2]), "+f"(c[3])
        : "r"(a[0]), "r"(a[1]), "r"(a[2]), "r"(a[3]), "r"(b[0]), "r"(b[1]));
}

// ---------------------------------------------------------------------------
// oproj tf32: gHid = LN1(x + gAgg @ Wo + bo); 512 thr, 128-row tiles, K=128
// ---------------------------------------------------------------------------
__global__ void oproj_tc_ln1(const float* __restrict__ x,
                             const float* __restrict__ Wo,
                             const float* __restrict__ bo,
                             const float* __restrict__ g1,
                             const float* __restrict__ bb1, int M) {
    __shared__ unsigned As[128][36];
    __shared__ unsigned Bs[32][132];
    __shared__ float rs[4][128];
    __shared__ float rq[4][128];
    int tid = threadIdx.x, lane = tid & 31, wid = tid >> 5;
    int wy = (wid & 3) * 32, wxg = wid >> 2;
    int wx = wxg * 32;
    int m0 = blockIdx.y * 128;
    int r = lane >> 2, t = lane & 3;
    float c[2][4][4];
#pragma unroll
    for (int i = 0; i < 2; i++)
#pragma unroll
        for (int j = 0; j < 4; j++)
#pragma unroll
            for (int q = 0; q < 4; q++) c[i][j][q] = 0.f;

    for (int k0 = 0; k0 < 128; k0 += 32) {
#pragma unroll
        for (int l = tid; l < 1024; l += 512) {
            int m = l >> 3, kq = (l & 7) << 2;
            int gm = m0 + m; if (gm >= M) gm = M - 1;
            float4 a = *(const float4*)(&gAgg[gm * 128 + k0 + kq]);
            As[m][kq] = f2tf(a.x); As[m][kq + 1] = f2tf(a.y);
            As[m][kq + 2] = f2tf(a.z); As[m][kq + 3] = f2tf(a.w);
        }
#pragma unroll
        for (int l = tid; l < 1024; l += 512) {
            int k = l >> 5, nq = (l & 31) << 2;
            float4 b = *(const float4*)(&Wo[(k0 + k) * 128 + nq]);
            Bs[k][nq] = f2tf(b.x); Bs[k][nq + 1] = f2tf(b.y);
            Bs[k][nq + 2] = f2tf(b.z); Bs[k][nq + 3] = f2tf(b.w);
        }
        __syncthreads();
#pragma unroll
        for (int kk = 0; kk < 32; kk += 8) {
            unsigned af[2][4], bf[4][2];
#pragma unroll
            for (int i = 0; i < 2; i++) {
                af[i][0] = As[wy + i * 16 + r][kk + t];
                af[i][1] = As[wy + i * 16 + r + 8][kk + t];
                af[i][2] = As[wy + i * 16 + r][kk + t + 4];
                af[i][3] = As[wy + i * 16 + r + 8][kk + t + 4];
            }
#pragma unroll
            for (int j = 0; j < 4; j++) {
                bf[j][0] = Bs[kk + t][wx + j * 8 + r];
                bf[j][1] = Bs[kk + t + 4][wx + j * 8 + r];
            }
#pragma unroll
            for (int i = 0; i < 2; i++)
#pragma unroll
                for (int j = 0; j < 4; j++) mma_tf32(c[i][j], af[i], bf[j]);
        }
        __syncthreads();
    }

    float sum[2][2] = {{0.f, 0.f}, {0.f, 0.f}};
    float sq2[2][2] = {{0.f, 0.f}, {0.f, 0.f}};
#pragma unroll
    for (int i = 0; i < 2; i++) {
        int row = m0 + wy + i * 16 + r;
        int rowc  = (row < M) ? row : (M - 1);
        int row2c = (row + 8 < M) ? (row + 8) : (M - 1);
#pragma unroll
        for (int j = 0; j < 4; j++) {
            int col = wx + j * 8 + 2 * t;
            float bc0 = bo[col], bc1 = bo[col + 1];
            float2 h0 = *(const float2*)&x[rowc * 128 + col];
            float2 h1 = *(const float2*)&x[row2c * 128 + col];
            c[i][j][0] += bc0 + h0.x;
            c[i][j][1] += bc1 + h0.y;
            c[i][j][2] += bc0 + h1.x;
            c[i][j][3] += bc1 + h1.y;
            sum[i][0] += c[i][j][0] + c[i][j][1];
            sum[i][1] += c[i][j][2] + c[i][j][3];
            sq2[i][0] = fmaf(c[i][j][0], c[i][j][0], fmaf(c[i][j][1], c[i][j][1], sq2[i][0]));
            sq2[i][1] = fmaf(c[i][j][2], c[i][j][2], fmaf(c[i][j][3], c[i][j][3], sq2[i][1]));
        }
    }
#pragma unroll
    for (int i = 0; i < 2; i++) {
#pragma unroll
        for (int hl = 0; hl < 2; hl++) {
            sum[i][hl] += __shfl_xor_sync(0xffffffffu, sum[i][hl], 1);
            sum[i][hl] += __shfl_xor_sync(0xffffffffu, sum[i][hl], 2);
            sq2[i][hl] += __shfl_xor_sync(0xffffffffu, sq2[i][hl], 1);
            sq2[i][hl] += __shfl_xor_sync(0xffffffffu, sq2[i][hl], 2);
        }
    }
    if (t == 0) {
#pragma unroll
        for (int i = 0; i < 2; i++) {
            rs[wxg][wy + i * 16 + r]     = sum[i][0];
            rs[wxg][wy + i * 16 + r + 8] = sum[i][1];
            rq[wxg][wy + i * 16 + r]     = sq2[i][0];
            rq[wxg][wy + i * 16 + r + 8] = sq2[i][1];
        }
    }
    __syncthreads();
#pragma unroll
    for (int i = 0; i < 2; i++) {
#pragma unroll
        for (int hl = 0; hl < 2; hl++) {
            int rl = wy + i * 16 + r + hl * 8;
            int row = m0 + rl;
            float s  = rs[0][rl] + rs[1][rl] + rs[2][rl] + rs[3][rl];
            float s2 = rq[0][rl] + rq[1][rl] + rq[2][rl] + rq[3][rl];
            float mean = s * (1.f / DIM);
            float var = s2 * (1.f / DIM) - mean * mean;
            float rstd = rsqrtf(var + 1e-5f);
            if (row < M) {
#pragma unroll
                for (int j = 0; j < 4; j++) {
                    int col = wx + j * 8 + 2 * t;
                    float y0 = c[i][j][hl * 2 + 0];
                    float y1 = c[i][j][hl * 2 + 1];
                    float o0 = (y0 - mean) * rstd * g1[col] + bb1[col];
                    float o1 = (y1 - mean) * rstd * g1[col + 1] + bb1[col + 1];
                    *(float2*)&gHid[row * 128 + col] = make_float2(o0, o1);
                }
            }
        }
    }
}

// ---------------------------------------------------------------------------
// FFN1: gF1[M,512] = gelu(gHid[M,128] @ W1 + b1) -> fp16; 512 thr
// ---------------------------------------------------------------------------
__global__ void ffn1_tc(const float* __restrict__ W1,
                        const float* __restrict__ b1v, int M) {
    __shared__ unsigned As[128][36];
    __shared__ unsigned Bs[32][132];
    int tid = threadIdx.x, lane = tid & 31, wid = tid >> 5;
    int wy = (wid & 3) * 32, wx = (wid >> 2) * 32;
    int m0 = blockIdx.y * 128, n0 = blockIdx.x * 128;
    int r = lane >> 2, t = lane & 3;
    float c[2][4][4];
#pragma unroll
    for (int i = 0; i < 2; i++)
#pragma unroll
        for (int j = 0; j < 4; j++)
#pragma unroll
            for (int q = 0; q < 4; q++) c[i][j][q] = 0.f;

    for (int k0 = 0; k0 < 128; k0 += 32) {
#pragma unroll
        for (int l = tid; l < 1024; l += 512) {
            int m = l >> 3, kq = (l & 7) << 2;
            int gm = m0 + m; if (gm >= M) gm = M - 1;
            float4 a = *(const float4*)(&gHid[gm * 128 + k0 + kq]);
            As[m][kq] = f2tf(a.x); As[m][kq + 1] = f2tf(a.y);
            As[m][kq + 2] = f2tf(a.z); As[m][kq + 3] = f2tf(a.w);
        }
#pragma unroll
        for (int l = tid; l < 1024; l += 512) {
            int k = l >> 5, nq = (l & 31) << 2;
            float4 b = *(const float4*)(&W1[(k0 + k) * 512 + n0 + nq]);
            Bs[k][nq] = f2tf(b.x); Bs[k][nq + 1] = f2tf(b.y);
            Bs[k][nq + 2] = f2tf(b.z); Bs[k][nq + 3] = f2tf(b.w);
        }
        __syncthreads();
#pragma unroll
        for (int kk = 0; kk < 32; kk += 8) {
            unsigned af[2][4], bf[4][2];
#pragma unroll
            for (int i = 0; i < 2; i++) {
                af[i][0] = As[wy + i * 16 + r][kk + t];
                af[i][1] = As[wy + i * 16 + r + 8][kk + t];
                af[i][2] = As[wy + i * 16 + r][kk + t + 4];
                af[i][3] = As[wy + i * 16 + r + 8][kk + t + 4];
            }
#pragma unroll
            for (int j = 0; j < 4; j++) {
                bf[j][0] = Bs[kk + t][wx + j * 8 + r];
                bf[j][1] = Bs[kk + t + 4][wx + j * 8 + r];
            }
#pragma unroll
            for (int i = 0; i < 2; i++)
#pragma unroll
                for (int j = 0; j < 4; j++) mma_tf32(c[i][j], af[i], bf[j]);
        }
        __syncthreads();
    }
#pragma unroll
    for (int i = 0; i < 2; i++) {
        int row = m0 + wy + i * 16 + r;
        int row2 = row + 8;
#pragma unroll
        for (int j = 0; j < 4; j++) {
            int col = n0 + wx + j * 8 + 2 * t;
            float bc0 = b1v[col], bc1 = b1v[col + 1];
            if (row < M) {
                float v0 = c[i][j][0] + bc0;
                float v1 = c[i][j][1] + bc1;
                v0 = 0.5f * v0 * (1.f + erff(v0 * 0.7071067811865476f));
                v1 = 0.5f * v1 * (1.f + erff(v1 * 0.7071067811865476f));
                *(__half2*)&gF1[row * 512 + col] = __floats2half2_rn(v0, v1);
            }
            if (row2 < M) {
                float v0 = c[i][j][2] + bc0;
                float v1 = c[i][j][3] + bc1;
                v0 = 0.5f * v0 * (1.f + erff(v0 * 0.7071067811865476f));
                v1 = 0.5f * v1 * (1.f + erff(v1 * 0.7071067811865476f));
                *(__half2*)&gF1[row2 * 512 + col] = __floats2half2_rn(v0, v1);
            }
        }
    }
}

// ---------------------------------------------------------------------------
// FFN2: out = LN2(gHid + gF1[M,512] @ W2 + b2); gF1 read as fp16; 512 thr
// ---------------------------------------------------------------------------
__global__ void ffn2_tc_ln2(const float* __restrict__ W2,
                            const float* __restrict__ b2v,
                            const float* __restrict__ g2,
                            const float* __restrict__ bb2,
                            float* __restrict__ out, int M) {
    __shared__ unsigned As[128][36];
    __shared__ unsigned Bs[32][132];
    __shared__ float rs[4][128];
    __shared__ float rq[4][128];
    int tid = threadIdx.x, lane = tid & 31, wid = tid >> 5;
    int wy = (wid & 3) * 32, wxg = wid >> 2;
    int wx = wxg * 32;
    int m0 = blockIdx.y * 128;
    int r = lane >> 2, t = lane & 3;
    float c[2][4][4];
#pragma unroll
    for (int i = 0; i < 2; i++)
#pragma unroll
        for (int j = 0; j < 4; j++)
#pragma unroll
            for (int q = 0; q < 4; q++) c[i][j][q] = 0.f;

    for (int k0 = 0; k0 < 512; k0 += 32) {
#pragma unroll
        for (int l = tid; l < 1024; l += 512) {
            int m = l >> 3, kq = (l & 7) << 2;
            int gm = m0 + m; if (gm >= M) gm = M - 1;
            uint2 araw = *(const uint2*)(&gF1[gm * 512 + k0 + kq]);
            float2 a01 = __half22float2(*(__half2*)&araw.x);
            float2 a23 = __half22float2(*(__half2*)&araw.y);
            As[m][kq] = f2tf(a01.x); As[m][kq + 1] = f2tf(a01.y);
            As[m][kq + 2] = f2tf(a23.x); As[m][kq + 3] = f2tf(a23.y);
        }
#pragma unroll
        for (int l = tid; l < 1024; l += 512) {
            int k = l >> 5, nq = (l & 31) << 2;
            float4 b = *(const float4*)(&W2[(k0 + k) * 128 + nq]);
            Bs[k][nq] = f2tf(b.x); Bs[k][nq + 1] = f2tf(b.y);
            Bs[k][nq + 2] = f2tf(b.z); Bs[k][nq + 3] = f2tf(b.w);
        }
        __syncthreads();
#pragma unroll
        for (int kk = 0; kk < 32; kk += 8) {
            unsigned af[2][4], bf[4][2];
#pragma unroll
            for (int i = 0; i < 2; i++) {
                af[i][0] = As[wy + i * 16 + r][kk + t];
                af[i][1] = As[wy + i * 16 + r + 8][kk + t];
                af[i][2] = As[wy + i * 16 + r][kk + t + 4];
                af[i][3] = As[wy + i * 16 + r + 8][kk + t + 4];
            }
#pragma unroll
            for (int j = 0; j < 4; j++) {
                bf[j][0] = Bs[kk + t][wx + j * 8 + r];
                bf[j][1] = Bs[kk + t + 4][wx + j * 8 + r];
            }
#pragma unroll
            for (int i = 0; i < 2; i++)
#pragma unroll
                for (int j = 0; j < 4; j++) mma_tf32(c[i][j], af[i], bf[j]);
        }
        __syncthreads();
    }

    float sum[2][2] = {{0.f, 0.f}, {0.f, 0.f}};
    float sq2[2][2] = {{0.f, 0.f}, {0.f, 0.f}};
#pragma unroll
    for (int i = 0; i < 2; i++) {
        int row = m0 + wy + i * 16 + r;
        int rowc  = (row < M) ? row : (M - 1);
        int row2c = (row + 8 < M) ? (row + 8) : (M - 1);
#pragma unroll
        for (int j = 0; j < 4; j++) {
            int col = wx + j * 8 + 2 * t;
            float bc0 = b2v[col], bc1 = b2v[col + 1];
            float2 h0 = *(const float2*)&gHid[rowc * 128 + col];
            float2 h1 = *(const float2*)&gHid[row2c * 128 + col];
            c[i][j][0] += bc0 + h0.x;
            c[i][j][1] += bc1 + h0.y;
            c[i][j][2] += bc0 + h1.x;
            c[i][j][3] += bc1 + h1.y;
            sum[i][0] += c[i][j][0] + c[i][j][1];
            sum[i][1] += c[i][j][2] + c[i][j][3];
            sq2[i][0] = fmaf(c[i][j][0], c[i][j][0], fmaf(c[i][j][1], c[i][j][1], sq2[i][0]));
            sq2[i][1] = fmaf(c[i][j][2], c[i][j][2], fmaf(c[i][j][3], c[i][j][3], sq2[i][1]));
        }
    }
#pragma unroll
    for (int i = 0; i < 2; i++) {
#pragma unroll
        for (int hl = 0; hl < 2; hl++) {
            sum[i][hl] += __shfl_xor_sync(0xffffffffu, sum[i][hl], 1);
            sum[i][hl] += __shfl_xor_sync(0xffffffffu, sum[i][hl], 2);
            sq2[i][hl] += __shfl_xor_sync(0xffffffffu, sq2[i][hl], 1);
            sq2[i][hl] += __shfl_xor_sync(0xffffffffu, sq2[i][hl], 2);
        }
    }
    if (t == 0) {
#pragma unroll
        for (int i = 0; i < 2; i++) {
            rs[wxg][wy + i * 16 + r]     = sum[i][0];
            rs[wxg][wy + i * 16 + r + 8] = sum[i][1];
            rq[wxg][wy + i * 16 + r]     = sq2[i][0];
            rq[wxg][wy + i * 16 + r + 8] = sq2[i][1];
        }
    }
    __syncthreads();
#pragma unroll
    for (int i = 0; i < 2; i++) {
#pragma unroll
        for (int hl = 0; hl < 2; hl++) {
            int rl = wy + i * 16 + r + hl * 8;
            int row = m0 + rl;
            float s  = rs[0][rl] + rs[1][rl] + rs[2][rl] + rs[3][rl];
            float s2 = rq[0][rl] + rq[1][rl] + rq[2][rl] + rq[3][rl];
            float mean = s * (1.f / DIM);
            float var = s2 * (1.f / DIM) - mean * mean;
            float rstd = rsqrtf(var + 1e-5f);
            if (row < M) {
#pragma unroll
                for (int j = 0; j < 4; j++) {
                    int col = wx + j * 8 + 2 * t;
                    float y0 = c[i][j][hl * 2 + 0];
                    float y1 = c[i][j][hl * 2 + 1];
                    float o0 = (y0 - mean) * rstd * g2[col] + bb2[col];
                    float o1 = (y1 - mean) * rstd * g2[col + 1] + bb2[col + 1];
                    *(float2*)&out[row * 128 + col] = make_float2(o0, o1);
                }
            }
        }
    }
}

// ---------------------------------------------------------------------------
extern "C" void kernel_launch(void* const* d_in, const int* in_sizes, int n_in,
                              void* d_out, int out_size) {
    const float* x     = (const float*)d_in[0];
    const int*   ei    = (const int*)d_in[1];
    const int*   etype = (const int*)d_in[2];
    const int*   ntype = (const int*)d_in[3];
    const float* WQ    = (const float*)d_in[4];
    const float* WK    = (const float*)d_in[5];
    const float* WV    = (const float*)d_in[6];
    const float* We    = (const float*)d_in[7];
    const float* mu    = (const float*)d_in[8];
    const float* Wo    = (const float*)d_in[9];
    const float* bo    = (const float*)d_in[10];
    const float* ln1g  = (const float*)d_in[11];
    const float* ln1b  = (const float*)d_in[12];
    const float* W1    = (const float*)d_in[13];
    const float* b1    = (const float*)d_in[14];
    const float* W2    = (const float*)d_in[15];
    const float* b2    = (const float*)d_in[16];
    const float* ln2g  = (const float*)d_in[17];
    const float* ln2b  = (const float*)d_in[18];

    int N = in_sizes[0] / DIM;   // 50000
    int E = in_sizes[1] / 2;     // 800000
    int nblk = (N + 1023) / 1024;
    int mtiles = (N + 127) / 128;

    init_kernel<<<(N + 255) / 256, 256>>>(N);
    qkv_kt_kernel<<<N, 128>>>(x, ntype, WQ, WK, WV, We);
    hist_kernel<<<(E + 255) / 256, 256>>>(ei, E);
    scan_local_kernel<<<nblk, 1024>>>(N);
    scan_block_kernel<<<1, 64>>>(nblk);
    scan_add_kernel<<<(N + 255) / 256, 256>>>(N, E);
    fill_kernel<<<(E + 255) / 256, 256>>>(ei, etype, E);
    attn_kernel<<<N, 128>>>(mu, E);
    oproj_tc_ln1<<<dim3(1, mtiles), 512>>>(x, Wo, bo, ln1g, ln1b, N);
    ffn1_tc<<<dim3(4, mtiles), 512>>>(W1, b1, N);
    ffn2_tc_ln2<<<dim3(1, mtiles), 512>>>(W2, b2, ln2g, ln2b, (float*)d_out, N);
}